// round 3
// baseline (speedup 1.0000x reference)
#include <cuda_runtime.h>
#include <cstdint>

// Problem constants
#define B_SZ   64
#define T_STEPS 1000
#define IN_F   512
#define OUT_F  512
#define M_TOTAL (B_SZ * T_STEPS)   // 64000

// Scratch (device globals: allocation-free at launch time)
__device__ float g_cur[(size_t)M_TOTAL * OUT_F];   // [b*T + t][o], 131 MB
__device__ float g_Rt[OUT_F * OUT_F];              // Rt[j][o] = R[o][j]

// ---------------------------------------------------------------------------
// R transpose: Rt[j][o] = R[o][j]
// ---------------------------------------------------------------------------
__global__ void transpose_kernel(const float* __restrict__ R) {
    __shared__ float tile[32][33];
    int jx = blockIdx.x * 32 + threadIdx.x;
    int oy = blockIdx.y * 32 + threadIdx.y;
    #pragma unroll
    for (int dy = 0; dy < 32; dy += 8)
        tile[threadIdx.y + dy][threadIdx.x] = R[(size_t)(oy + dy) * OUT_F + jx];
    __syncthreads();
    int ox = blockIdx.y * 32 + threadIdx.x;
    int jy = blockIdx.x * 32 + threadIdx.y;
    #pragma unroll
    for (int dy = 0; dy < 32; dy += 8)
        g_Rt[(size_t)(jy + dy) * OUT_F + ox] = tile[threadIdx.x][threadIdx.y + dy];
}

// ---------------------------------------------------------------------------
// Packed fp32x2 helpers (Blackwell FFMA2 — only reachable via inline PTX)
// ---------------------------------------------------------------------------
__device__ __forceinline__ unsigned long long pack_bcast(float v) {
    unsigned long long p;
    asm("mov.b64 %0, {%1, %1};" : "=l"(p) : "r"(__float_as_uint(v)));
    return p;
}
__device__ __forceinline__ unsigned long long fma2(unsigned long long a,
                                                   unsigned long long b,
                                                   unsigned long long c) {
    unsigned long long d;
    asm("fma.rn.f32x2 %0, %1, %2, %3;" : "=l"(d) : "l"(a), "l"(b), "l"(c));
    return d;
}

// ---------------------------------------------------------------------------
// Input GEMM: g_cur[m][n] = bias[n] + sum_k x[m][k] * W[n][k]
// M=64000, N=512, K=512.
// BM=256, BN=128, BK=8, 256 threads. Each thread: 16(m) x 8(n) outputs held
// as 64 packed f32x2 accumulators (2 adjacent m-rows per 64-bit register).
// ---------------------------------------------------------------------------
#define BM 256
#define BN 128
#define BK 8

__global__ __launch_bounds__(256, 1) void gemm_kernel(
    const float* __restrict__ A,     // x      [M][512]
    const float* __restrict__ W,     // weight [512][512]
    const float* __restrict__ bias)  // [512]
{
    __shared__ float As[BK][BM];
    __shared__ float Bs[BK][BN];

    const int tid   = threadIdx.x;
    const int mBase = blockIdx.y * BM;
    const int nBase = blockIdx.x * BN;

    // A loads: thread tid loads row (mBase+tid), k0..k0+7 (2 float4)
    const float* aPtr = A + (size_t)(mBase + tid) * IN_F;
    // B loads: thread loads row (nBase + tid/2), 4 floats at k0 + (tid&1)*4
    const int bRow = tid >> 1;
    const int bCol = (tid & 1) * 4;
    const float* wPtr = W + (size_t)(nBase + bRow) * IN_F + bCol;

    const int tRow = (tid >> 4) * 16;   // 0..240 (16 m-rows = 8 pairs)
    const int tCol = (tid & 15) * 8;    // 0..120

    unsigned long long acc[8][8];
    #pragma unroll
    for (int i = 0; i < 8; i++)
        #pragma unroll
        for (int j = 0; j < 8; j++)
            acc[i][j] = 0ull;

    // register-staged prefetch
    float4 a0 = *(const float4*)(aPtr + 0);
    float4 a1 = *(const float4*)(aPtr + 4);
    float4 b0 = *(const float4*)(wPtr + 0);

    for (int k0 = 0; k0 < IN_F; k0 += BK) {
        As[0][tid] = a0.x; As[1][tid] = a0.y; As[2][tid] = a0.z; As[3][tid] = a0.w;
        As[4][tid] = a1.x; As[5][tid] = a1.y; As[6][tid] = a1.z; As[7][tid] = a1.w;
        Bs[bCol + 0][bRow] = b0.x;
        Bs[bCol + 1][bRow] = b0.y;
        Bs[bCol + 2][bRow] = b0.z;
        Bs[bCol + 3][bRow] = b0.w;
        __syncthreads();

        if (k0 + BK < IN_F) {   // prefetch next k-block while computing
            a0 = *(const float4*)(aPtr + k0 + 8);
            a1 = *(const float4*)(aPtr + k0 + 12);
            b0 = *(const float4*)(wPtr + k0 + 8);
        }

        #pragma unroll
        for (int kk = 0; kk < BK; kk++) {
            unsigned long long rm[8];
            const ulonglong2* pA = (const ulonglong2*)&As[kk][tRow];
            ulonglong2 r0 = pA[0], r1 = pA[1], r2 = pA[2], r3 = pA[3];
            rm[0] = r0.x; rm[1] = r0.y; rm[2] = r1.x; rm[3] = r1.y;
            rm[4] = r2.x; rm[5] = r2.y; rm[6] = r3.x; rm[7] = r3.y;

            const float4* pB = (const float4*)&Bs[kk][tCol];
            float4 q0 = pB[0], q1 = pB[1];
            unsigned long long rn[8];
            rn[0] = pack_bcast(q0.x); rn[1] = pack_bcast(q0.y);
            rn[2] = pack_bcast(q0.z); rn[3] = pack_bcast(q0.w);
            rn[4] = pack_bcast(q1.x); rn[5] = pack_bcast(q1.y);
            rn[6] = pack_bcast(q1.z); rn[7] = pack_bcast(q1.w);

            #pragma unroll
            for (int i = 0; i < 8; i++)
                #pragma unroll
                for (int j = 0; j < 8; j++)
                    acc[i][j] = fma2(rm[i], rn[j], acc[i][j]);
        }
        __syncthreads();
    }

    float4 bz0 = *(const float4*)(bias + nBase + tCol);
    float4 bz1 = *(const float4*)(bias + nBase + tCol + 4);
    const float bz[8] = {bz0.x, bz0.y, bz0.z, bz0.w, bz1.x, bz1.y, bz1.z, bz1.w};

    #pragma unroll
    for (int i = 0; i < 8; i++) {
        float lo[8], hi[8];
        #pragma unroll
        for (int j = 0; j < 8; j++) {
            lo[j] = __uint_as_float((unsigned)(acc[i][j] & 0xffffffffull)) + bz[j];
            hi[j] = __uint_as_float((unsigned)(acc[i][j] >> 32)) + bz[j];
        }
        size_t row0 = (size_t)(mBase + tRow + 2 * i);
        float* p0 = &g_cur[row0 * OUT_F + nBase + tCol];
        float* p1 = p0 + OUT_F;
        *(float4*)(p0 + 0) = make_float4(lo[0], lo[1], lo[2], lo[3]);
        *(float4*)(p0 + 4) = make_float4(lo[4], lo[5], lo[6], lo[7]);
        *(float4*)(p1 + 0) = make_float4(hi[0], hi[1], hi[2], hi[3]);
        *(float4*)(p1 + 4) = make_float4(hi[4], hi[5], hi[6], hi[7]);
    }
}

// ---------------------------------------------------------------------------
// Sequential ALIF scan: 1 CTA per batch element, 1 thread per neuron.
// Binary z kept as ballot words; double-buffered masks -> ONE sync per step.
// ---------------------------------------------------------------------------
__global__ __launch_bounds__(OUT_F) void scan_kernel(
    const float* __restrict__ beta,
    const float* __restrict__ beta2,
    const float* __restrict__ decay_v,
    const float* __restrict__ decay_b,
    float* __restrict__ out,
    int write_states)
{
    const int b    = blockIdx.x;
    const int o    = threadIdx.x;
    const int warp = o >> 5;
    const int lane = o & 31;

    __shared__ unsigned zmask[2][OUT_F / 32];

    const float bt  = beta[o];
    const float bt2 = beta2[o];
    const float dv  = decay_v[o];
    const float db  = decay_b[o];
    const float odv = 1.f - dv;
    const float odb = 1.f - db;

    float v = 0.f, z = 0.f, ba = 0.f;

    float* zs   = out;
    float* vful = out + (size_t)B_SZ * T_STEPS * OUT_F;
    float* zful = vful + (size_t)B_SZ * (T_STEPS + 1) * OUT_F;
    float* bful = zful + (size_t)B_SZ * (T_STEPS + 1) * OUT_F;

    if (write_states) {
        size_t p = (size_t)b * (T_STEPS + 1) * OUT_F + o;   // t = 0 pad rows
        vful[p] = 0.f; zful[p] = 0.f; bful[p] = 0.f;
    }

    const float* curb = g_cur + ((size_t)b * T_STEPS) * OUT_F + o;
    float c0 = curb[0];
    float c1 = curb[OUT_F];

    if (o < 2 * (OUT_F / 32)) ((unsigned*)zmask)[o] = 0u;
    __syncthreads();

    size_t zsIdx = ((size_t)b * T_STEPS) * OUT_F + o;
    size_t stIdx = ((size_t)b * (T_STEPS + 1) + 1) * OUT_F + o;
    int cur = 0;

    for (int t = 0; t < T_STEPS; t++) {
        float cnext = (t + 2 < T_STEPS) ? curb[(size_t)(t + 2) * OUT_F] : 0.f;

        // recurrent input from previous-step spikes
        float rec = 0.f;
        #pragma unroll
        for (int w = 0; w < OUT_F / 32; w++) {
            unsigned m = zmask[cur][w];
            while (m) {
                int j = (w << 5) + (__ffs(m) - 1);
                m &= m - 1;
                rec += g_Rt[(size_t)j * OUT_F + o];
            }
        }

        float cc = c0 + rec;
        v  = v * (1.f - z);
        v  = dv * v + odv * (cc - ba);
        z  = (v >= 1.f) ? 1.f : 0.f;
        ba = db * ba + odb * (bt * v + bt2 * z);

        zs[zsIdx] = z;
        if (write_states) {
            vful[stIdx] = v;
            zful[stIdx] = z;
            bful[stIdx] = ba;
        }

        unsigned ball = __ballot_sync(0xffffffffu, z >= 1.f);
        if (lane == 0) zmask[cur ^ 1][warp] = ball;
        __syncthreads();          // next-step masks visible; old buffer free
        cur ^= 1;

        c0 = c1; c1 = cnext;
        zsIdx += OUT_F;
        stIdx += OUT_F;
    }
}

// ---------------------------------------------------------------------------
extern "C" void kernel_launch(void* const* d_in, const int* in_sizes, int n_in,
                              void* d_out, int out_size) {
    const float* x     = (const float*)d_in[0];
    const float* wgt   = (const float*)d_in[1];
    const float* bias  = (const float*)d_in[2];
    const float* rec   = (const float*)d_in[3];
    const float* beta  = (const float*)d_in[4];
    const float* beta2 = (const float*)d_in[5];
    const float* dv    = (const float*)d_in[6];
    const float* db    = (const float*)d_in[7];
    float* out = (float*)d_out;

    dim3 tb(32, 8), tg(16, 16);
    transpose_kernel<<<tg, tb>>>(rec);

    dim3 gg(OUT_F / BN, M_TOTAL / BM);
    gemm_kernel<<<gg, 256>>>(x, wgt, bias);

    int write_states = (out_size > B_SZ * T_STEPS * OUT_F) ? 1 : 0;
    scan_kernel<<<B_SZ, OUT_F>>>(beta, beta2, dv, db, out, write_states);
}

// round 6
// speedup vs baseline: 2.3050x; 2.3050x over previous
#include <cuda_runtime.h>
#include <cuda_bf16.h>
#include <cstdint>

// Problem constants
#define B_SZ   64
#define T_STEPS 1000
#define IN_F   512
#define OUT_F  512
#define M_TOTAL (B_SZ * T_STEPS)   // 64000

// Scratch (device globals: allocation-free)
__device__ float g_cur[(size_t)M_TOTAL * OUT_F];          // 131 MB fp32
__device__ float g_Rt[OUT_F * OUT_F];
__device__ __nv_bfloat16 g_Ahi[(size_t)M_TOTAL * IN_F];   // 65.5 MB
__device__ __nv_bfloat16 g_Alo[(size_t)M_TOTAL * IN_F];
__device__ __nv_bfloat16 g_Whi[OUT_F * IN_F];
__device__ __nv_bfloat16 g_Wlo[OUT_F * IN_F];

// ---------------------------------------------------------------------------
// Helpers
// ---------------------------------------------------------------------------
__device__ __forceinline__ uint32_t smem_u32(const void* p) {
    uint32_t a;
    asm("{ .reg .u64 t; cvta.to.shared.u64 t, %1; cvt.u32.u64 %0, t; }"
        : "=r"(a) : "l"(p));
    return a;
}
#define SW128(o) ((o) ^ (((o) >> 3) & 0x70))

__device__ __forceinline__ void cp16(uint32_t dst, const void* src) {
    asm volatile("cp.async.cg.shared.global [%0], [%1], 16;"
                 :: "r"(dst), "l"(src));
}
#define CP_COMMIT() asm volatile("cp.async.commit_group;" ::: "memory")
#define CP_WAIT(n)  asm volatile("cp.async.wait_group %0;" :: "n"(n) : "memory")

__device__ __forceinline__ void ldsm4(uint32_t* r, uint32_t addr) {
    asm volatile("ldmatrix.sync.aligned.m8n8.x4.shared.b16 {%0,%1,%2,%3}, [%4];"
                 : "=r"(r[0]), "=r"(r[1]), "=r"(r[2]), "=r"(r[3]) : "r"(addr));
}

__device__ __forceinline__ void mma16816(float* d, const uint32_t* a,
                                         uint32_t b0, uint32_t b1) {
    asm volatile(
        "mma.sync.aligned.m16n8k16.row.col.f32.bf16.bf16.f32 "
        "{%0,%1,%2,%3}, {%4,%5,%6,%7}, {%8,%9}, {%0,%1,%2,%3};"
        : "+f"(d[0]), "+f"(d[1]), "+f"(d[2]), "+f"(d[3])
        : "r"(a[0]), "r"(a[1]), "r"(a[2]), "r"(a[3]), "r"(b0), "r"(b1));
}

// ---------------------------------------------------------------------------
// R transpose: Rt[j][o] = R[o][j]
// ---------------------------------------------------------------------------
__global__ void transpose_kernel(const float* __restrict__ R) {
    __shared__ float tile[32][33];
    int jx = blockIdx.x * 32 + threadIdx.x;
    int oy = blockIdx.y * 32 + threadIdx.y;
    #pragma unroll
    for (int dy = 0; dy < 32; dy += 8)
        tile[threadIdx.y + dy][threadIdx.x] = R[(size_t)(oy + dy) * OUT_F + jx];
    __syncthreads();
    int ox = blockIdx.y * 32 + threadIdx.x;
    int jy = blockIdx.x * 32 + threadIdx.y;
    #pragma unroll
    for (int dy = 0; dy < 32; dy += 8)
        g_Rt[(size_t)(jy + dy) * OUT_F + ox] = tile[threadIdx.x][threadIdx.y + dy];
}

// ---------------------------------------------------------------------------
// fp32 -> (hi, lo) bf16 split
// ---------------------------------------------------------------------------
__device__ __forceinline__ void split_bf16(float f, unsigned short& h, unsigned short& l) {
    __nv_bfloat16 hb = __float2bfloat16_rn(f);
    __nv_bfloat16 lb = __float2bfloat16_rn(f - __bfloat162float(hb));
    h = __bfloat16_as_ushort(hb);
    l = __bfloat16_as_ushort(lb);
}

__global__ void convert_x_kernel(const float* __restrict__ x) {
    size_t total4 = (size_t)M_TOTAL * IN_F / 4;
    for (size_t i = (size_t)blockIdx.x * blockDim.x + threadIdx.x; i < total4;
         i += (size_t)gridDim.x * blockDim.x) {
        float4 v = *(const float4*)(x + i * 4);
        unsigned short h0, h1, h2, h3, l0, l1, l2, l3;
        split_bf16(v.x, h0, l0); split_bf16(v.y, h1, l1);
        split_bf16(v.z, h2, l2); split_bf16(v.w, h3, l3);
        uint2 hp = make_uint2((uint32_t)h0 | ((uint32_t)h1 << 16),
                              (uint32_t)h2 | ((uint32_t)h3 << 16));
        uint2 lp = make_uint2((uint32_t)l0 | ((uint32_t)l1 << 16),
                              (uint32_t)l2 | ((uint32_t)l3 << 16));
        *(uint2*)((char*)g_Ahi + i * 8) = hp;
        *(uint2*)((char*)g_Alo + i * 8) = lp;
    }
}

__global__ void convert_w_kernel(const float* __restrict__ w) {
    size_t total4 = (size_t)OUT_F * IN_F / 4;
    for (size_t i = (size_t)blockIdx.x * blockDim.x + threadIdx.x; i < total4;
         i += (size_t)gridDim.x * blockDim.x) {
        float4 v = *(const float4*)(w + i * 4);
        unsigned short h0, h1, h2, h3, l0, l1, l2, l3;
        split_bf16(v.x, h0, l0); split_bf16(v.y, h1, l1);
        split_bf16(v.z, h2, l2); split_bf16(v.w, h3, l3);
        uint2 hp = make_uint2((uint32_t)h0 | ((uint32_t)h1 << 16),
                              (uint32_t)h2 | ((uint32_t)h3 << 16));
        uint2 lp = make_uint2((uint32_t)l0 | ((uint32_t)l1 << 16),
                              (uint32_t)l2 | ((uint32_t)l3 << 16));
        *(uint2*)((char*)g_Whi + i * 8) = hp;
        *(uint2*)((char*)g_Wlo + i * 8) = lp;
    }
}

// ---------------------------------------------------------------------------
// GEMM via mma.sync bf16 split: g_cur = x @ W^T
//   D += Ahi*Whi + Ahi*Wlo + Alo*Whi   (all three per K-chunk, one K sweep)
// BM=128, BN=256, BK=64, 256 threads (8 warps: 4m x 2n), warp tile 32x128.
// SW128-swizzled smem, cp.async double-buffered (2 x 96 KB).
// ---------------------------------------------------------------------------
#define GBUF   98304
#define OFF_AHI 0
#define OFF_ALO 16384
#define OFF_WHI 32768
#define OFF_WLO 65536
#define NKITER  8          // 512 / 64

__device__ __forceinline__ void gemm_fill(uint32_t sbase, int buf, int kc,
                                          int mBase, int nBase, int tid) {
    uint32_t b = sbase + buf * GBUF;
    // A tiles: 128 rows x 8 chunks of 16B = 1024 chunks each (hi, lo)
    #pragma unroll
    for (int j = 0; j < 4; j++) {
        int c = tid + j * 256;
        int row = c >> 3, seg = c & 7;
        uint32_t sw = SW128((uint32_t)(row * 128 + seg * 16));
        size_t gofs = (size_t)(mBase + row) * IN_F + kc + seg * 8;
        cp16(b + OFF_AHI + sw, g_Ahi + gofs);
        cp16(b + OFF_ALO + sw, g_Alo + gofs);
    }
    // W tiles: 256 rows x 8 chunks = 2048 chunks each (hi, lo)
    #pragma unroll
    for (int j = 0; j < 8; j++) {
        int c = tid + j * 256;
        int row = c >> 3, seg = c & 7;
        uint32_t sw = SW128((uint32_t)(row * 128 + seg * 16));
        size_t gofs = (size_t)(nBase + row) * IN_F + kc + seg * 8;
        cp16(b + OFF_WHI + sw, g_Whi + gofs);
        cp16(b + OFF_WLO + sw, g_Wlo + gofs);
    }
}

__global__ __launch_bounds__(256, 1) void gemm_mma_kernel() {
    extern __shared__ __align__(1024) unsigned char sm[];
    const int tid    = threadIdx.x;
    const int lane   = tid & 31;
    const int wid    = tid >> 5;
    const int warp_m = wid & 3;      // 0..3 -> m offset *32
    const int warp_n = wid >> 2;     // 0..1 -> n offset *128
    const int mBase  = blockIdx.y * 128;
    const int nBase  = blockIdx.x * 256;
    const uint32_t sbase = smem_u32(sm);

    float acc[2][16][4];
    #pragma unroll
    for (int i = 0; i < 2; i++)
        #pragma unroll
        for (int j = 0; j < 16; j++)
            #pragma unroll
            for (int r = 0; r < 4; r++)
                acc[i][j][r] = 0.f;

    // ldmatrix lane address components (within a 128B-row SW128 tile)
    const int aRow = warp_m * 32 + (lane & 15);          // + mt*16
    const int aCsel = lane >> 4;                          // 0/1 -> k-halves
    const int bRow = warp_n * 128 + (lane & 7) + (lane >> 4) * 8;  // + np*16
    const int bCsel = (lane >> 3) & 1;

    gemm_fill(sbase, 0, 0, mBase, nBase, tid);
    CP_COMMIT();

    for (int it = 0; it < NKITER; it++) {
        const int cur = it & 1;
        if (it + 1 < NKITER) {
            gemm_fill(sbase, cur ^ 1, (it + 1) * 64, mBase, nBase, tid);
            CP_COMMIT();
            CP_WAIT(1);
        } else {
            CP_WAIT(0);
        }
        __syncthreads();

        const uint32_t aHi = sbase + cur * GBUF + OFF_AHI;
        const uint32_t aLo = sbase + cur * GBUF + OFF_ALO;
        const uint32_t wHi = sbase + cur * GBUF + OFF_WHI;
        const uint32_t wLo = sbase + cur * GBUF + OFF_WLO;

        #pragma unroll
        for (int kt = 0; kt < 4; kt++) {
            uint32_t ah[2][4], al[2][4];
            #pragma unroll
            for (int mt = 0; mt < 2; mt++) {
                uint32_t off = SW128((uint32_t)((aRow + mt * 16) * 128 +
                                                (2 * kt + aCsel) * 16));
                ldsm4(ah[mt], aHi + off);
                ldsm4(al[mt], aLo + off);
            }
            #pragma unroll
            for (int np = 0; np < 8; np++) {
                uint32_t off = SW128((uint32_t)((bRow + np * 16) * 128 +
                                                (2 * kt + bCsel) * 16));
                uint32_t wh[4], wl[4];
                ldsm4(wh, wHi + off);
                ldsm4(wl, wLo + off);
                #pragma unroll
                for (int sub = 0; sub < 2; sub++) {
                    const int nt = np * 2 + sub;
                    const uint32_t bh0 = wh[sub * 2], bh1 = wh[sub * 2 + 1];
                    const uint32_t bl0 = wl[sub * 2], bl1 = wl[sub * 2 + 1];
                    #pragma unroll
                    for (int mt = 0; mt < 2; mt++) {
                        mma16816(acc[mt][nt], ah[mt], bh0, bh1);  // Ahi*Whi
                        mma16816(acc[mt][nt], al[mt], bh0, bh1);  // Alo*Whi
                        mma16816(acc[mt][nt], ah[mt], bl0, bl1);  // Ahi*Wlo
                    }
                }
            }
        }
        __syncthreads();
    }

    // Epilogue: direct STG (float2 per fragment row; 32B-sector aligned)
    #pragma unroll
    for (int mt = 0; mt < 2; mt++) {
        #pragma unroll
        for (int nt = 0; nt < 16; nt++) {
            int m0 = mBase + warp_m * 32 + mt * 16 + (lane >> 2);
            int n0 = nBase + warp_n * 128 + nt * 8 + (lane & 3) * 2;
            *(float2*)&g_cur[(size_t)m0 * OUT_F + n0] =
                make_float2(acc[mt][nt][0], acc[mt][nt][1]);
            *(float2*)&g_cur[(size_t)(m0 + 8) * OUT_F + n0] =
                make_float2(acc[mt][nt][2], acc[mt][nt][3]);
        }
    }
}

// ---------------------------------------------------------------------------
// Sequential ALIF scan (bias folded in): 1 CTA/batch, 1 thread/neuron.
// ---------------------------------------------------------------------------
__global__ __launch_bounds__(OUT_F) void scan_kernel(
    const float* __restrict__ bias,
    const float* __restrict__ beta,
    const float* __restrict__ beta2,
    const float* __restrict__ decay_v,
    const float* __restrict__ decay_b,
    float* __restrict__ out,
    int write_states)
{
    const int b    = blockIdx.x;
    const int o    = threadIdx.x;
    const int warp = o >> 5;
    const int lane = o & 31;

    __shared__ unsigned zmask[2][OUT_F / 32];

    const float bs  = bias[o];
    const float bt  = beta[o];
    const float bt2 = beta2[o];
    const float dv  = decay_v[o];
    const float db  = decay_b[o];
    const float odv = 1.f - dv;
    const float odb = 1.f - db;

    float v = 0.f, z = 0.f, ba = 0.f;

    float* zs   = out;
    float* vful = out + (size_t)B_SZ * T_STEPS * OUT_F;
    float* zful = vful + (size_t)B_SZ * (T_STEPS + 1) * OUT_F;
    float* bful = zful + (size_t)B_SZ * (T_STEPS + 1) * OUT_F;

    if (write_states) {
        size_t p = (size_t)b * (T_STEPS + 1) * OUT_F + o;   // t = 0 pad rows
        vful[p] = 0.f; zful[p] = 0.f; bful[p] = 0.f;
    }

    const float* curb = g_cur + ((size_t)b * T_STEPS) * OUT_F + o;
    float c0 = curb[0];
    float c1 = curb[OUT_F];

    if (o < 2 * (OUT_F / 32)) ((unsigned*)zmask)[o] = 0u;
    __syncthreads();

    size_t zsIdx = ((size_t)b * T_STEPS) * OUT_F + o;
    size_t stIdx = ((size_t)b * (T_STEPS + 1) + 1) * OUT_F + o;
    int cur = 0;

    for (int t = 0; t < T_STEPS; t++) {
        float cnext = (t + 2 < T_STEPS) ? curb[(size_t)(t + 2) * OUT_F] : 0.f;

        float rec = 0.f;
        #pragma unroll
        for (int w = 0; w < OUT_F / 32; w++) {
            unsigned m = zmask[cur][w];
            while (m) {
                int j = (w << 5) + (__ffs(m) - 1);
                m &= m - 1;
                rec += g_Rt[(size_t)j * OUT_F + o];
            }
        }

        float cc = c0 + bs + rec;
        v  = v * (1.f - z);
        v  = dv * v + odv * (cc - ba);
        z  = (v >= 1.f) ? 1.f : 0.f;
        ba = db * ba + odb * (bt * v + bt2 * z);

        zs[zsIdx] = z;
        if (write_states) {
            vful[stIdx] = v;
            zful[stIdx] = z;
            bful[stIdx] = ba;
        }

        unsigned ball = __ballot_sync(0xffffffffu, z >= 1.f);
        if (lane == 0) zmask[cur ^ 1][warp] = ball;
        __syncthreads();
        cur ^= 1;

        c0 = c1; c1 = cnext;
        zsIdx += OUT_F;
        stIdx += OUT_F;
    }
}

// ---------------------------------------------------------------------------
extern "C" void kernel_launch(void* const* d_in, const int* in_sizes, int n_in,
                              void* d_out, int out_size) {
    const float* x     = (const float*)d_in[0];
    const float* wgt   = (const float*)d_in[1];
    const float* bias  = (const float*)d_in[2];
    const float* rec   = (const float*)d_in[3];
    const float* beta  = (const float*)d_in[4];
    const float* beta2 = (const float*)d_in[5];
    const float* dv    = (const float*)d_in[6];
    const float* db    = (const float*)d_in[7];
    float* out = (float*)d_out;

    (void)cudaFuncSetAttribute(gemm_mma_kernel,
                               cudaFuncAttributeMaxDynamicSharedMemorySize,
                               2 * GBUF);

    dim3 tb(32, 8), tg(16, 16);
    transpose_kernel<<<tg, tb>>>(rec);

    convert_x_kernel<<<4096, 256>>>(x);
    convert_w_kernel<<<256, 256>>>(wgt);

    dim3 gg(OUT_F / 256, M_TOTAL / 128);   // (2, 500)
    gemm_mma_kernel<<<gg, 256, 2 * GBUF>>>();

    int write_states = (out_size > B_SZ * T_STEPS * OUT_F) ? 1 : 0;
    scan_kernel<<<B_SZ, OUT_F>>>(bias, beta, beta2, dv, db, out, write_states);
}

// round 8
// speedup vs baseline: 3.2171x; 1.3957x over previous
#include <cuda_runtime.h>
#include <cuda_bf16.h>
#include <cstdint>

// Problem constants
#define B_SZ   64
#define T_STEPS 1000
#define IN_F   512
#define OUT_F  512
#define M_TOTAL (B_SZ * T_STEPS)   // 64000

// Scratch (device globals: allocation-free)
__device__ float g_cur[(size_t)M_TOTAL * OUT_F];          // 131 MB fp32
__device__ float g_Rt[OUT_F * OUT_F];
__device__ __nv_bfloat16 g_Ahi[(size_t)M_TOTAL * IN_F];   // 65.5 MB
__device__ __nv_bfloat16 g_Alo[(size_t)M_TOTAL * IN_F];
__device__ __nv_bfloat16 g_Whi[OUT_F * IN_F];
__device__ __nv_bfloat16 g_Wlo[OUT_F * IN_F];

// ---------------------------------------------------------------------------
// Helpers
// ---------------------------------------------------------------------------
__device__ __forceinline__ uint32_t smem_u32(const void* p) {
    uint32_t a;
    asm("{ .reg .u64 t; cvta.to.shared.u64 t, %1; cvt.u32.u64 %0, t; }"
        : "=r"(a) : "l"(p));
    return a;
}
#define SW128(o) ((o) ^ (((o) >> 3) & 0x70))

__device__ __forceinline__ void cp16(uint32_t dst, const void* src) {
    asm volatile("cp.async.cg.shared.global [%0], [%1], 16;"
                 :: "r"(dst), "l"(src));
}
#define CP_COMMIT() asm volatile("cp.async.commit_group;" ::: "memory")
#define CP_WAIT(n)  asm volatile("cp.async.wait_group %0;" :: "n"(n) : "memory")

__device__ __forceinline__ void ldsm4(uint32_t* r, uint32_t addr) {
    asm volatile("ldmatrix.sync.aligned.m8n8.x4.shared.b16 {%0,%1,%2,%3}, [%4];"
                 : "=r"(r[0]), "=r"(r[1]), "=r"(r[2]), "=r"(r[3]) : "r"(addr));
}

__device__ __forceinline__ void mma16816(float* d, const uint32_t* a,
                                         uint32_t b0, uint32_t b1) {
    asm volatile(
        "mma.sync.aligned.m16n8k16.row.col.f32.bf16.bf16.f32 "
        "{%0,%1,%2,%3}, {%4,%5,%6,%7}, {%8,%9}, {%0,%1,%2,%3};"
        : "+f"(d[0]), "+f"(d[1]), "+f"(d[2]), "+f"(d[3])
        : "r"(a[0]), "r"(a[1]), "r"(a[2]), "r"(a[3]), "r"(b0), "r"(b1));
}

// ---------------------------------------------------------------------------
// R transpose: Rt[j][o] = R[o][j]
// ---------------------------------------------------------------------------
__global__ void transpose_kernel(const float* __restrict__ R) {
    __shared__ float tile[32][33];
    int jx = blockIdx.x * 32 + threadIdx.x;
    int oy = blockIdx.y * 32 + threadIdx.y;
    #pragma unroll
    for (int dy = 0; dy < 32; dy += 8)
        tile[threadIdx.y + dy][threadIdx.x] = R[(size_t)(oy + dy) * OUT_F + jx];
    __syncthreads();
    int ox = blockIdx.y * 32 + threadIdx.x;
    int jy = blockIdx.x * 32 + threadIdx.y;
    #pragma unroll
    for (int dy = 0; dy < 32; dy += 8)
        g_Rt[(size_t)(jy + dy) * OUT_F + ox] = tile[threadIdx.x][threadIdx.y + dy];
}

// ---------------------------------------------------------------------------
// fp32 -> (hi, lo) bf16 split
// ---------------------------------------------------------------------------
__device__ __forceinline__ void split_bf16(float f, unsigned short& h, unsigned short& l) {
    __nv_bfloat16 hb = __float2bfloat16_rn(f);
    __nv_bfloat16 lb = __float2bfloat16_rn(f - __bfloat162float(hb));
    h = __bfloat16_as_ushort(hb);
    l = __bfloat16_as_ushort(lb);
}

__global__ void convert_x_kernel(const float* __restrict__ x) {
    size_t total4 = (size_t)M_TOTAL * IN_F / 4;
    for (size_t i = (size_t)blockIdx.x * blockDim.x + threadIdx.x; i < total4;
         i += (size_t)gridDim.x * blockDim.x) {
        float4 v = *(const float4*)(x + i * 4);
        unsigned short h0, h1, h2, h3, l0, l1, l2, l3;
        split_bf16(v.x, h0, l0); split_bf16(v.y, h1, l1);
        split_bf16(v.z, h2, l2); split_bf16(v.w, h3, l3);
        uint2 hp = make_uint2((uint32_t)h0 | ((uint32_t)h1 << 16),
                              (uint32_t)h2 | ((uint32_t)h3 << 16));
        uint2 lp = make_uint2((uint32_t)l0 | ((uint32_t)l1 << 16),
                              (uint32_t)l2 | ((uint32_t)l3 << 16));
        *(uint2*)((char*)g_Ahi + i * 8) = hp;
        *(uint2*)((char*)g_Alo + i * 8) = lp;
    }
}

__global__ void convert_w_kernel(const float* __restrict__ w) {
    size_t total4 = (size_t)OUT_F * IN_F / 4;
    for (size_t i = (size_t)blockIdx.x * blockDim.x + threadIdx.x; i < total4;
         i += (size_t)gridDim.x * blockDim.x) {
        float4 v = *(const float4*)(w + i * 4);
        unsigned short h0, h1, h2, h3, l0, l1, l2, l3;
        split_bf16(v.x, h0, l0); split_bf16(v.y, h1, l1);
        split_bf16(v.z, h2, l2); split_bf16(v.w, h3, l3);
        uint2 hp = make_uint2((uint32_t)h0 | ((uint32_t)h1 << 16),
                              (uint32_t)h2 | ((uint32_t)h3 << 16));
        uint2 lp = make_uint2((uint32_t)l0 | ((uint32_t)l1 << 16),
                              (uint32_t)l2 | ((uint32_t)l3 << 16));
        *(uint2*)((char*)g_Whi + i * 8) = hp;
        *(uint2*)((char*)g_Wlo + i * 8) = lp;
    }
}

// ---------------------------------------------------------------------------
// GEMM via mma.sync bf16 split (unchanged from R6: 238us, tensor=70.5%)
// ---------------------------------------------------------------------------
#define GBUF   98304
#define OFF_AHI 0
#define OFF_ALO 16384
#define OFF_WHI 32768
#define OFF_WLO 65536
#define NKITER  8          // 512 / 64

__device__ __forceinline__ void gemm_fill(uint32_t sbase, int buf, int kc,
                                          int mBase, int nBase, int tid) {
    uint32_t b = sbase + buf * GBUF;
    #pragma unroll
    for (int j = 0; j < 4; j++) {
        int c = tid + j * 256;
        int row = c >> 3, seg = c & 7;
        uint32_t sw = SW128((uint32_t)(row * 128 + seg * 16));
        size_t gofs = (size_t)(mBase + row) * IN_F + kc + seg * 8;
        cp16(b + OFF_AHI + sw, g_Ahi + gofs);
        cp16(b + OFF_ALO + sw, g_Alo + gofs);
    }
    #pragma unroll
    for (int j = 0; j < 8; j++) {
        int c = tid + j * 256;
        int row = c >> 3, seg = c & 7;
        uint32_t sw = SW128((uint32_t)(row * 128 + seg * 16));
        size_t gofs = (size_t)(nBase + row) * IN_F + kc + seg * 8;
        cp16(b + OFF_WHI + sw, g_Whi + gofs);
        cp16(b + OFF_WLO + sw, g_Wlo + gofs);
    }
}

__global__ __launch_bounds__(256, 1) void gemm_mma_kernel() {
    extern __shared__ __align__(1024) unsigned char sm[];
    const int tid    = threadIdx.x;
    const int lane   = tid & 31;
    const int wid    = tid >> 5;
    const int warp_m = wid & 3;
    const int warp_n = wid >> 2;
    const int mBase  = blockIdx.y * 128;
    const int nBase  = blockIdx.x * 256;
    const uint32_t sbase = smem_u32(sm);

    float acc[2][16][4];
    #pragma unroll
    for (int i = 0; i < 2; i++)
        #pragma unroll
        for (int j = 0; j < 16; j++)
            #pragma unroll
            for (int r = 0; r < 4; r++)
                acc[i][j][r] = 0.f;

    const int aRow = warp_m * 32 + (lane & 15);
    const int aCsel = lane >> 4;
    const int bRow = warp_n * 128 + (lane & 7) + (lane >> 4) * 8;
    const int bCsel = (lane >> 3) & 1;

    gemm_fill(sbase, 0, 0, mBase, nBase, tid);
    CP_COMMIT();

    for (int it = 0; it < NKITER; it++) {
        const int cur = it & 1;
        if (it + 1 < NKITER) {
            gemm_fill(sbase, cur ^ 1, (it + 1) * 64, mBase, nBase, tid);
            CP_COMMIT();
            CP_WAIT(1);
        } else {
            CP_WAIT(0);
        }
        __syncthreads();

        const uint32_t aHi = sbase + cur * GBUF + OFF_AHI;
        const uint32_t aLo = sbase + cur * GBUF + OFF_ALO;
        const uint32_t wHi = sbase + cur * GBUF + OFF_WHI;
        const uint32_t wLo = sbase + cur * GBUF + OFF_WLO;

        #pragma unroll
        for (int kt = 0; kt < 4; kt++) {
            uint32_t ah[2][4], al[2][4];
            #pragma unroll
            for (int mt = 0; mt < 2; mt++) {
                uint32_t off = SW128((uint32_t)((aRow + mt * 16) * 128 +
                                                (2 * kt + aCsel) * 16));
                ldsm4(ah[mt], aHi + off);
                ldsm4(al[mt], aLo + off);
            }
            #pragma unroll
            for (int np = 0; np < 8; np++) {
                uint32_t off = SW128((uint32_t)((bRow + np * 16) * 128 +
                                                (2 * kt + bCsel) * 16));
                uint32_t wh[4], wl[4];
                ldsm4(wh, wHi + off);
                ldsm4(wl, wLo + off);
                #pragma unroll
                for (int sub = 0; sub < 2; sub++) {
                    const int nt = np * 2 + sub;
                    const uint32_t bh0 = wh[sub * 2], bh1 = wh[sub * 2 + 1];
                    const uint32_t bl0 = wl[sub * 2], bl1 = wl[sub * 2 + 1];
                    #pragma unroll
                    for (int mt = 0; mt < 2; mt++) {
                        mma16816(acc[mt][nt], ah[mt], bh0, bh1);
                        mma16816(acc[mt][nt], al[mt], bh0, bh1);
                        mma16816(acc[mt][nt], ah[mt], bl0, bl1);
                    }
                }
            }
        }
        __syncthreads();
    }

    #pragma unroll
    for (int mt = 0; mt < 2; mt++) {
        #pragma unroll
        for (int nt = 0; nt < 16; nt++) {
            int m0 = mBase + warp_m * 32 + mt * 16 + (lane >> 2);
            int n0 = nBase + warp_n * 128 + nt * 8 + (lane & 3) * 2;
            *(float2*)&g_cur[(size_t)m0 * OUT_F + n0] =
                make_float2(acc[mt][nt][0], acc[mt][nt][1]);
            *(float2*)&g_cur[(size_t)(m0 + 8) * OUT_F + n0] =
                make_float2(acc[mt][nt][2], acc[mt][nt][3]);
        }
    }
}

// ---------------------------------------------------------------------------
// Sequential ALIF scan: 1 CTA/batch, 1 thread/neuron.
//  - mask scan: 4 x LDS.128 + register OR-reduce + ONE uniform branch
//  - global prefetch ring depth 4 (register ring, unroll 4)
// ---------------------------------------------------------------------------
__global__ __launch_bounds__(OUT_F) void scan_kernel(
    const float* __restrict__ bias,
    const float* __restrict__ beta,
    const float* __restrict__ beta2,
    const float* __restrict__ decay_v,
    const float* __restrict__ decay_b,
    float* __restrict__ out,
    int write_states)
{
    const int b    = blockIdx.x;
    const int o    = threadIdx.x;
    const int warp = o >> 5;
    const int lane = o & 31;

    __shared__ __align__(16) unsigned zmask[2][16];

    const float bs  = bias[o];
    const float bt  = beta[o];
    const float bt2 = beta2[o];
    const float dv  = decay_v[o];
    const float db  = decay_b[o];
    const float odv = 1.f - dv;
    const float odb = 1.f - db;

    float v = 0.f, z = 0.f, ba = 0.f;

    float* zs   = out;
    float* vful = out + (size_t)B_SZ * T_STEPS * OUT_F;
    float* zful = vful + (size_t)B_SZ * (T_STEPS + 1) * OUT_F;
    float* bful = zful + (size_t)B_SZ * (T_STEPS + 1) * OUT_F;

    if (write_states) {
        size_t p = (size_t)b * (T_STEPS + 1) * OUT_F + o;   // t = 0 pad rows
        vful[p] = 0.f; zful[p] = 0.f; bful[p] = 0.f;
    }

    const float* curb = g_cur + ((size_t)b * T_STEPS) * OUT_F + o;

    // prefetch ring, depth 4
    float c[4];
    c[0] = curb[0];
    c[1] = curb[(size_t)1 * OUT_F];
    c[2] = curb[(size_t)2 * OUT_F];
    c[3] = curb[(size_t)3 * OUT_F];

    if (o < 32) ((unsigned*)zmask)[o] = 0u;
    __syncthreads();

    size_t zsIdx = ((size_t)b * T_STEPS) * OUT_F + o;
    size_t stIdx = ((size_t)b * (T_STEPS + 1) + 1) * OUT_F + o;
    int cur = 0;

    #pragma unroll 4
    for (int t = 0; t < T_STEPS; t++) {
        const int slot = t & 3;
        const float cin = c[slot];
        if (t + 4 < T_STEPS) c[slot] = curb[(size_t)(t + 4) * OUT_F];

        // ---- spike gather: 4 x LDS.128, one branch ----
        const uint4* mw = (const uint4*)zmask[cur];
        uint4 q0 = mw[0], q1 = mw[1], q2 = mw[2], q3 = mw[3];
        unsigned any = q0.x | q0.y | q0.z | q0.w
                     | q1.x | q1.y | q1.z | q1.w
                     | q2.x | q2.y | q2.z | q2.w
                     | q3.x | q3.y | q3.z | q3.w;
        float rec = 0.f;
        if (any) {
            unsigned mwv[16] = {q0.x, q0.y, q0.z, q0.w, q1.x, q1.y, q1.z, q1.w,
                                q2.x, q2.y, q2.z, q2.w, q3.x, q3.y, q3.z, q3.w};
            #pragma unroll
            for (int w = 0; w < 16; w++) {
                unsigned m = mwv[w];
                while (m) {
                    int j = (w << 5) + (__ffs(m) - 1);
                    m &= m - 1;
                    rec += g_Rt[(size_t)j * OUT_F + o];
                }
            }
        }

        const float cc = cin + bs + rec;
        v  = v * (1.f - z);
        v  = dv * v + odv * (cc - ba);
        z  = (v >= 1.f) ? 1.f : 0.f;
        ba = db * ba + odb * (bt * v + bt2 * z);

        zs[zsIdx] = z;
        if (write_states) {
            vful[stIdx] = v;
            zful[stIdx] = z;
            bful[stIdx] = ba;
        }

        unsigned ball = __ballot_sync(0xffffffffu, z >= 1.f);
        if (lane == 0) zmask[cur ^ 1][warp] = ball;
        __syncthreads();
        cur ^= 1;

        zsIdx += OUT_F;
        stIdx += OUT_F;
    }
}

// ---------------------------------------------------------------------------
extern "C" void kernel_launch(void* const* d_in, const int* in_sizes, int n_in,
                              void* d_out, int out_size) {
    const float* x     = (const float*)d_in[0];
    const float* wgt   = (const float*)d_in[1];
    const float* bias  = (const float*)d_in[2];
    const float* rec   = (const float*)d_in[3];
    const float* beta  = (const float*)d_in[4];
    const float* beta2 = (const float*)d_in[5];
    const float* dv    = (const float*)d_in[6];
    const float* db    = (const float*)d_in[7];
    float* out = (float*)d_out;

    (void)cudaFuncSetAttribute(gemm_mma_kernel,
                               cudaFuncAttributeMaxDynamicSharedMemorySize,
                               2 * GBUF);

    dim3 tb(32, 8), tg(16, 16);
    transpose_kernel<<<tg, tb>>>(rec);

    convert_x_kernel<<<4096, 256>>>(x);
    convert_w_kernel<<<256, 256>>>(wgt);

    dim3 gg(OUT_F / 256, M_TOTAL / 128);   // (2, 500)
    gemm_mma_kernel<<<gg, 256, 2 * GBUF>>>();

    int write_states = (out_size > B_SZ * T_STEPS * OUT_F) ? 1 : 0;
    scan_kernel<<<B_SZ, OUT_F>>>(bias, beta, beta2, dv, db, out, write_states);
}